// round 3
// baseline (speedup 1.0000x reference)
#include <cuda_runtime.h>

#define B_   64
#define D_   2048
#define E_   64
#define H1_  512
#define H2_  256
#define EPSF 1e-5f

#define TM   64      // rows per CTA tile (one b, contiguous k)
#define KC   32      // K-chunk
#define ASTR 36      // padded stride for Ash [m][h]

// ---------------- scratch (device globals: no allocation allowed) -----------
__device__ float gA [B_ * H1_];    // s1*(rep@W1d + b1) + t1
__device__ float gC [D_ * H1_];    // s1*(emb@W1e)
__device__ float gWd[D_ * H1_];    // s1*W1d
__device__ float gW2[H1_ * H2_];   // s2*W2
__device__ float gc2[H2_];         // s2*b2 + t2

using u64 = unsigned long long;

__device__ __forceinline__ u64 fma2(u64 a, u64 b, u64 c) {
    u64 d;
    asm("fma.rn.f32x2 %0, %1, %2, %3;" : "=l"(d) : "l"(a), "l"(b), "l"(c));
    return d;
}
__device__ __forceinline__ u64 pack2(float x, float y) {
    u64 d;
    asm("mov.b64 %0, {%1, %2};" : "=l"(d) : "f"(x), "f"(y));
    return d;
}
__device__ __forceinline__ float2 unpack2(u64 v) {
    float2 r;
    asm("mov.b64 {%0, %1}, %2;" : "=f"(r.x), "=f"(r.y) : "l"(v));
    return r;
}

// ---------------- prep kernels ---------------------------------------------

// gA[b,h] = s1[h]*(sum_d rep[b,d]*W1d[d,h] + b1[h]) + t1[h]
__global__ void prep_base(const float* __restrict__ rep, const float* __restrict__ W1,
                          const float* __restrict__ b1,  const float* __restrict__ g1,
                          const float* __restrict__ beta1, const float* __restrict__ m1,
                          const float* __restrict__ v1) {
    int h = threadIdx.x;   // 512
    int b = blockIdx.x;    // 64
    float s1 = g1[h] * rsqrtf(v1[h] + EPSF);
    float t1 = beta1[h] - m1[h] * s1;
    const float* repb = rep + b * D_;
    float acc = b1[h];
#pragma unroll 8
    for (int d = 0; d < D_; ++d)
        acc = fmaf(repb[d], W1[d * H1_ + h], acc);
    gA[b * H1_ + h] = s1 * acc + t1;
}

// gC[k,h] = s1[h]*sum_e emb[k,e]*W1e[e,h]
__global__ void prep_emb(const float* __restrict__ emb, const float* __restrict__ W1,
                         const float* __restrict__ g1,  const float* __restrict__ v1) {
    int h = threadIdx.x;   // 512
    int k = blockIdx.x;    // 2048
    float s1 = g1[h] * rsqrtf(v1[h] + EPSF);
    const float* ek  = emb + k * E_;
    const float* W1e = W1 + D_ * H1_;
    float acc = 0.f;
#pragma unroll
    for (int e = 0; e < E_; ++e)
        acc = fmaf(ek[e], W1e[e * H1_ + h], acc);
    gC[k * H1_ + h] = s1 * acc;
}

// gWd = s1*W1d  (elementwise, float4)
__global__ void prep_wd(const float* __restrict__ W1, const float* __restrict__ g1,
                        const float* __restrict__ v1) {
    int i  = blockIdx.x * blockDim.x + threadIdx.x;   // f4 index, D_*H1_/4 total
    int h0 = (i * 4) & (H1_ - 1);
    float4 w = ((const float4*)W1)[i];
    float4 o;
    o.x = w.x * (g1[h0 + 0] * rsqrtf(v1[h0 + 0] + EPSF));
    o.y = w.y * (g1[h0 + 1] * rsqrtf(v1[h0 + 1] + EPSF));
    o.z = w.z * (g1[h0 + 2] * rsqrtf(v1[h0 + 2] + EPSF));
    o.w = w.w * (g1[h0 + 3] * rsqrtf(v1[h0 + 3] + EPSF));
    ((float4*)gWd)[i] = o;
}

// gW2 = s2*W2 ; gc2 = s2*b2 + (beta2 - m2*s2)
__global__ void prep_w2(const float* __restrict__ W2, const float* __restrict__ b2,
                        const float* __restrict__ g2, const float* __restrict__ beta2,
                        const float* __restrict__ m2, const float* __restrict__ v2) {
    int i  = blockIdx.x * blockDim.x + threadIdx.x;   // f4 index, H1_*H2_/4 total
    int o0 = (i * 4) & (H2_ - 1);
    float4 w = ((const float4*)W2)[i];
    float4 r;
    r.x = w.x * (g2[o0 + 0] * rsqrtf(v2[o0 + 0] + EPSF));
    r.y = w.y * (g2[o0 + 1] * rsqrtf(v2[o0 + 1] + EPSF));
    r.z = w.z * (g2[o0 + 2] * rsqrtf(v2[o0 + 2] + EPSF));
    r.w = w.w * (g2[o0 + 3] * rsqrtf(v2[o0 + 3] + EPSF));
    ((float4*)gW2)[i] = r;
    if (blockIdx.x == 0) {
        int o = threadIdx.x;  // 256
        float s2 = g2[o] * rsqrtf(v2[o] + EPSF);
        gc2[o] = s2 * b2[o] + (beta2[o] - m2[o] * s2);
    }
}

// ---------------- main fused kernel ----------------------------------------
// Each CTA: 64 rows (one b, k0..k0+63) x 256 out-cols, K=512 in 16 chunks.
__global__ __launch_bounds__(256)
void main_kernel(const float* __restrict__ rep, const float* __restrict__ W3,
                 const float* __restrict__ b3, float* __restrict__ out) {
    __shared__ float Ash[TM * ASTR];   // h1 tile, [m][h] padded (9216 B)
    __shared__ float Bsh[KC * H2_];    // W2' tile, [kk][n]   (32768 B)
    __shared__ float reps[TM];

    const int tid  = threadIdx.x;
    const int lane = tid & 31;
    const int warp = tid >> 5;
    const int bidx = blockIdx.x;
    const int b    = bidx >> 5;            // 32 tiles per b (D_/TM)
    const int k0   = (bidx & 31) * TM;

    if (tid < TM) reps[tid] = rep[b * D_ + k0 + tid];

    const float* gAb = gA + b * H1_;
    const int n0   = lane * 4;
    const int n1   = 128 + lane * 4;
    const int row0 = warp * 8;

    u64 acc[8][4];
#pragma unroll
    for (int r = 0; r < 8; ++r)
#pragma unroll
        for (int p = 0; p < 4; ++p) acc[r][p] = 0ull;

    for (int ch = 0; ch < H1_ / KC; ++ch) {
        const int h0 = ch * KC;
        __syncthreads();
        // stage W2' chunk: 32x256 floats = 2048 float4, 8 per thread
        {
            const float4* src = (const float4*)(gW2 + h0 * H2_);
#pragma unroll
            for (int it = 0; it < 8; ++it)
                ((float4*)Bsh)[tid + it * 256] = src[tid + it * 256];
        }
        // build h1 tile: 64x32 = 512 quads, 2 per thread
#pragma unroll
        for (int it = 0; it < 2; ++it) {
            int idx = tid + it * 256;
            int m   = idx >> 3;
            int hl  = (idx & 7) * 4;
            int k   = k0 + m;
            float4 c4 = *(const float4*)(gC  + k * H1_ + h0 + hl);
            float4 w4 = *(const float4*)(gWd + k * H1_ + h0 + hl);
            float4 a4 = *(const float4*)(gAb + h0 + hl);
            float  rm = reps[m];
            float4 hv;
            hv.x = fmaxf(fmaf(-rm, w4.x, a4.x + c4.x), 0.f);
            hv.y = fmaxf(fmaf(-rm, w4.y, a4.y + c4.y), 0.f);
            hv.z = fmaxf(fmaf(-rm, w4.z, a4.z + c4.z), 0.f);
            hv.w = fmaxf(fmaf(-rm, w4.w, a4.w + c4.w), 0.f);
            *(float4*)(Ash + m * ASTR + hl) = hv;
        }
        __syncthreads();
        // FFMA2 micro-GEMM: 8 rows x 8 cols per thread
#pragma unroll 8
        for (int kk = 0; kk < KC; ++kk) {
            ulonglong2 bv0 = *(const ulonglong2*)(Bsh + kk * H2_ + n0);
            ulonglong2 bv1 = *(const ulonglong2*)(Bsh + kk * H2_ + n1);
#pragma unroll
            for (int r = 0; r < 8; ++r) {
                float a = Ash[(row0 + r) * ASTR + kk];   // warp-broadcast
                u64 aa = pack2(a, a);
                acc[r][0] = fma2(aa, bv0.x, acc[r][0]);
                acc[r][1] = fma2(aa, bv0.y, acc[r][1]);
                acc[r][2] = fma2(aa, bv1.x, acc[r][2]);
                acc[r][3] = fma2(aa, bv1.y, acc[r][3]);
            }
        }
    }

    // epilogue: relu(acc + c2) . W3, warp-reduce over the 256 cols
    float c2v[8], w3v[8];
#pragma unroll
    for (int j = 0; j < 4; ++j) {
        c2v[j]     = gc2[n0 + j];  w3v[j]     = W3[n0 + j];
        c2v[4 + j] = gc2[n1 + j];  w3v[4 + j] = W3[n1 + j];
    }
    float bias = b3[0];
#pragma unroll
    for (int r = 0; r < 8; ++r) {
        float part = 0.f;
#pragma unroll
        for (int p = 0; p < 4; ++p) {
            float2 f = unpack2(acc[r][p]);
            int j = (p < 2) ? p * 2 : 4 + (p - 2) * 2;
            part += fmaxf(f.x + c2v[j],     0.f) * w3v[j];
            part += fmaxf(f.y + c2v[j + 1], 0.f) * w3v[j + 1];
        }
#pragma unroll
        for (int off = 16; off; off >>= 1)
            part += __shfl_xor_sync(0xffffffffu, part, off);
        if (lane == 0) out[b * D_ + k0 + row0 + r] = part + bias;
    }
}

// ---------------- launch ----------------------------------------------------
extern "C" void kernel_launch(void* const* d_in, const int* in_sizes, int n_in,
                              void* d_out, int out_size) {
    const float* rep   = (const float*)d_in[0];
    const float* emb   = (const float*)d_in[1];
    const float* W1    = (const float*)d_in[2];
    const float* b1    = (const float*)d_in[3];
    const float* g1    = (const float*)d_in[4];
    const float* beta1 = (const float*)d_in[5];
    const float* m1    = (const float*)d_in[6];
    const float* v1    = (const float*)d_in[7];
    const float* W2    = (const float*)d_in[8];
    const float* b2    = (const float*)d_in[9];
    const float* g2    = (const float*)d_in[10];
    const float* beta2 = (const float*)d_in[11];
    const float* m2    = (const float*)d_in[12];
    const float* v2    = (const float*)d_in[13];
    const float* W3    = (const float*)d_in[14];
    const float* b3    = (const float*)d_in[15];
    float* out = (float*)d_out;

    prep_base<<<B_, H1_>>>(rep, W1, b1, g1, beta1, m1, v1);
    prep_emb <<<D_, H1_>>>(emb, W1, g1, v1);
    prep_wd  <<<(D_ * H1_ / 4) / 256, 256>>>(W1, g1, v1);
    prep_w2  <<<(H1_ * H2_ / 4) / 256, 256>>>(W2, b2, g2, beta2, m2, v2);
    main_kernel<<<(B_ * D_) / TM, 256>>>(rep, W3, b3, out);
}

// round 7
// speedup vs baseline: 1.7759x; 1.7759x over previous
#include <cuda_runtime.h>
#include <cuda_bf16.h>
#include <cstdint>

#define B_   64
#define D_   2048
#define E_   64
#define H1_  512
#define H2_  256
#define EPSF 1e-5f

// ---- main-kernel tiling ----
#define BG    2                      // b per CTA
#define KG    64                     // k per CTA (rows = BG*KG = 128)
#define KCH   64                     // GEMM-K (h) chunk
#define NCH   (H1_ / KCH)            // 8
#define NCTA  ((B_ / BG) * (D_ / KG))    // 1024
#define NTHR  512                    // 16 warps: 2 (m) x 8 (n)

// ---- dynamic SMEM layout (bytes) ----
#define SM_REPS   0                  // 128 floats
#define SM_C2     512                // 256 floats
#define SM_W3     1536               // 256 floats
#define SM_RED    2560               // 128 x 8 floats = 4 KB
#define SM_AHI    8192               // 128 rows x 128 B = 16 KB
#define SM_ALO    24576              // 16 KB
#define SM_BHI    40960              // 256 rows x 128 B = 32 KB
#define SM_BLO    73728              // 32 KB
#define SM_TOTAL  106496

#define SW(o) ((o) ^ (((o) >> 3) & 0x70))

// ---- scratch (device globals; no allocation allowed) ----
__device__ float gA [B_ * H1_];     // s1*(rep@W1d + b1) + t1
__device__ float gC [D_ * H1_];     // s1*(emb@W1e)
__device__ float gWd[D_ * H1_];     // s1*W1d
__device__ float gc2[H2_];          // s2*b2 + t2
__device__ __align__(16) unsigned char gBhi[H1_ * H2_ * 2];  // W2' hi, SMEM chunk-image
__device__ __align__(16) unsigned char gBlo[H1_ * H2_ * 2];  // W2' lo, SMEM chunk-image

// ---------------- helpers ----------------
__device__ __forceinline__ uint32_t smem_u32(const void* p) {
    uint32_t a;
    asm("{ .reg .u64 t; cvta.to.shared.u64 t, %1; cvt.u32.u64 %0, t; }" : "=r"(a) : "l"(p));
    return a;
}
__device__ __forceinline__ unsigned short f2bf(float x) {
    unsigned short r;
    asm("cvt.rn.bf16.f32 %0, %1;" : "=h"(r) : "f"(x));
    return r;
}
// packed bf16x2: upper half <- a, lower half <- b
__device__ __forceinline__ uint32_t bf2pk(float a, float b) {
    uint32_t r;
    asm("cvt.rn.bf16x2.f32 %0, %1, %2;" : "=r"(r) : "f"(a), "f"(b));
    return r;
}
__device__ __forceinline__ float pk_lo(uint32_t p) { return __uint_as_float(p << 16); }
__device__ __forceinline__ float pk_hi(uint32_t p) { return __uint_as_float(p & 0xffff0000u); }

__device__ __forceinline__ void ldsm4(uint32_t& r0, uint32_t& r1, uint32_t& r2, uint32_t& r3,
                                      uint32_t addr) {
    asm volatile("ldmatrix.sync.aligned.m8n8.x4.shared.b16 {%0,%1,%2,%3}, [%4];"
                 : "=r"(r0), "=r"(r1), "=r"(r2), "=r"(r3) : "r"(addr));
}
__device__ __forceinline__ void mma_bf16(float* d, uint32_t a0, uint32_t a1, uint32_t a2,
                                         uint32_t a3, uint32_t b0, uint32_t b1) {
    asm volatile(
        "mma.sync.aligned.m16n8k16.row.col.f32.bf16.bf16.f32 "
        "{%0,%1,%2,%3}, {%4,%5,%6,%7}, {%8,%9}, {%0,%1,%2,%3};"
        : "+f"(d[0]), "+f"(d[1]), "+f"(d[2]), "+f"(d[3])
        : "r"(a0), "r"(a1), "r"(a2), "r"(a3), "r"(b0), "r"(b1));
}

// ---------------- prep kernels ----------------

__global__ void prep_base(const float* __restrict__ rep, const float* __restrict__ W1,
                          const float* __restrict__ b1,  const float* __restrict__ g1,
                          const float* __restrict__ beta1, const float* __restrict__ m1,
                          const float* __restrict__ v1) {
    int h  = blockIdx.x * 128 + threadIdx.x;
    int b0 = blockIdx.y * 4;
    const float* r0 = rep + (b0 + 0) * D_;
    const float* r1 = rep + (b0 + 1) * D_;
    const float* r2 = rep + (b0 + 2) * D_;
    const float* r3 = rep + (b0 + 3) * D_;
    float bv = b1[h];
    float a0 = bv, a1 = bv, a2 = bv, a3 = bv;
#pragma unroll 4
    for (int d = 0; d < D_; ++d) {
        float w = W1[d * H1_ + h];
        a0 = fmaf(__ldg(r0 + d), w, a0);
        a1 = fmaf(__ldg(r1 + d), w, a1);
        a2 = fmaf(__ldg(r2 + d), w, a2);
        a3 = fmaf(__ldg(r3 + d), w, a3);
    }
    float s1 = g1[h] * rsqrtf(v1[h] + EPSF);
    float t1 = beta1[h] - m1[h] * s1;
    gA[(b0 + 0) * H1_ + h] = s1 * a0 + t1;
    gA[(b0 + 1) * H1_ + h] = s1 * a1 + t1;
    gA[(b0 + 2) * H1_ + h] = s1 * a2 + t1;
    gA[(b0 + 3) * H1_ + h] = s1 * a3 + t1;
}

__global__ void prep_emb(const float* __restrict__ emb, const float* __restrict__ W1,
                         const float* __restrict__ g1,  const float* __restrict__ v1) {
    int h = threadIdx.x;
    int k = blockIdx.x;
    float s1 = g1[h] * rsqrtf(v1[h] + EPSF);
    const float* ek  = emb + k * E_;
    const float* W1e = W1 + D_ * H1_;
    float acc = 0.f;
#pragma unroll
    for (int e = 0; e < E_; ++e)
        acc = fmaf(ek[e], W1e[e * H1_ + h], acc);
    gC[k * H1_ + h] = s1 * acc;
}

__global__ void prep_wd(const float* __restrict__ W1, const float* __restrict__ g1,
                        const float* __restrict__ v1) {
    int i  = blockIdx.x * blockDim.x + threadIdx.x;
    int h0 = (i * 4) & (H1_ - 1);
    float4 w = ((const float4*)W1)[i];
    float4 o;
    o.x = w.x * (g1[h0 + 0] * rsqrtf(v1[h0 + 0] + EPSF));
    o.y = w.y * (g1[h0 + 1] * rsqrtf(v1[h0 + 1] + EPSF));
    o.z = w.z * (g1[h0 + 2] * rsqrtf(v1[h0 + 2] + EPSF));
    o.w = w.w * (g1[h0 + 3] * rsqrtf(v1[h0 + 3] + EPSF));
    ((float4*)gWd)[i] = o;
}

// W2' = s2*W2 split into bf16 hi/lo, stored as 8 chunk-images:
// chunk c: rows n=0..255, cols k_local=0..63 bf16 (128 B/row), SW128-swizzled.
__global__ void prep_w2(const float* __restrict__ W2, const float* __restrict__ b2,
                        const float* __restrict__ g2, const float* __restrict__ beta2,
                        const float* __restrict__ m2, const float* __restrict__ v2) {
    int idx = blockIdx.x * 256 + threadIdx.x;   // 131072
    int n = idx >> 9;
    int k = idx & 511;
    float s2 = g2[n] * rsqrtf(v2[n] + EPSF);
    float val = W2[k * H2_ + n] * s2;
    unsigned short hb = f2bf(val);
    float hf = __uint_as_float(((uint32_t)hb) << 16);
    unsigned short lb = f2bf(val - hf);
    int off = (k >> 6) * 32768 + SW(n * 128 + (k & 63) * 2);
    *(unsigned short*)(gBhi + off) = hb;
    *(unsigned short*)(gBlo + off) = lb;
    if (blockIdx.x == 0) {
        int o = threadIdx.x;
        float s = g2[o] * rsqrtf(v2[o] + EPSF);
        gc2[o] = s * b2[o] + (beta2[o] - m2[o] * s);
    }
}

// ---------------- main fused mma.sync kernel ----------------

__global__ __launch_bounds__(NTHR, 1)
void main_kernel(const float* __restrict__ rep, const float* __restrict__ W3,
                 const float* __restrict__ b3, float* __restrict__ out) {
    extern __shared__ unsigned char smem[];
    const uint32_t sbase = smem_u32(smem);
    float* reps = (float*)(smem + SM_REPS);
    float* c2s  = (float*)(smem + SM_C2);
    float* w3s  = (float*)(smem + SM_W3);
    float* red  = (float*)(smem + SM_RED);

    const int tid  = threadIdx.x;
    const int lane = tid & 31;
    const int warp = tid >> 5;
    const int wm   = warp >> 3;          // 0..1  -> m block of 64 rows
    const int wn   = warp & 7;           // 0..7  -> n block of 32 cols
    const int bb   = blockIdx.x >> 5;
    const int kb   = blockIdx.x & 31;
    const int b0   = bb * BG;
    const int k0   = kb * KG;

    if (tid < 128) reps[tid] = rep[(b0 + (tid >> 6)) * D_ + k0 + (tid & 63)];
    if (tid < 256) { c2s[tid] = gc2[tid]; w3s[tid] = W3[tid]; }
    __syncthreads();

    // per-lane ldmatrix address components
    const int li   = lane & 7;
    const int tsel = lane >> 3;
    const uint32_t rowoff = (tsel & 1) * 1024 + li * 128;
    const uint32_t kx     = (tsel >> 1) * 16;
    const uint32_t swm    = li << 4;
    const uint32_t aHiB = sbase + SM_AHI + wm * 8192 + rowoff;
    const uint32_t aLoB = sbase + SM_ALO + wm * 8192 + rowoff;
    const uint32_t bHiB = sbase + SM_BHI + wn * 4096 + rowoff;
    const uint32_t bLoB = sbase + SM_BLO + wn * 4096 + rowoff;

    float acc[4][4][4];
#pragma unroll
    for (int mi = 0; mi < 4; ++mi)
#pragma unroll
        for (int ni = 0; ni < 4; ++ni)
#pragma unroll
            for (int j = 0; j < 4; ++j) acc[mi][ni][j] = 0.f;

    for (int ch = 0; ch < NCH; ++ch) {
        const int h0 = ch * KCH;
        // ---- build A tile (h1 hi/lo, 128x64 bf16, swizzled) ----
#pragma unroll
        for (int uu = 0; uu < 4; ++uu) {
            int q   = tid + uu * NTHR;       // 0..2047
            int m   = q >> 4;                // 0..127
            int hq  = q & 15;                // quad within chunk
            int k_i = m & 63;
            int bi  = m >> 6;
            const float4 c4 = *(const float4*)(gC  + (k0 + k_i) * H1_ + h0 + hq * 4);
            const float4 w4 = *(const float4*)(gWd + (k0 + k_i) * H1_ + h0 + hq * 4);
            const float4 a4 = *(const float4*)(gA  + (b0 + bi) * H1_ + h0 + hq * 4);
            float rm = reps[m];
            float f0 = fmaxf(fmaf(-rm, w4.x, a4.x + c4.x), 0.f);
            float f1 = fmaxf(fmaf(-rm, w4.y, a4.y + c4.y), 0.f);
            float f2 = fmaxf(fmaf(-rm, w4.z, a4.z + c4.z), 0.f);
            float f3 = fmaxf(fmaf(-rm, w4.w, a4.w + c4.w), 0.f);
            uint32_t h01 = bf2pk(f1, f0);
            uint32_t h23 = bf2pk(f3, f2);
            float l0 = f0 - pk_lo(h01), l1 = f1 - pk_hi(h01);
            float l2 = f2 - pk_lo(h23), l3 = f3 - pk_hi(h23);
            uint32_t l01 = bf2pk(l1, l0);
            uint32_t l23 = bf2pk(l3, l2);
            int off = SW(m * 128 + hq * 8);
            *(uint2*)(smem + SM_AHI + off) = make_uint2(h01, h23);
            *(uint2*)(smem + SM_ALO + off) = make_uint2(l01, l23);
        }
        // ---- copy B chunk images (hi/lo, 32 KB each) ----
        {
            const float4* sh = (const float4*)(gBhi + ch * 32768);
            const float4* sl = (const float4*)(gBlo + ch * 32768);
            float4* dh = (float4*)(smem + SM_BHI);
            float4* dl = (float4*)(smem + SM_BLO);
#pragma unroll
            for (int i = 0; i < 4; ++i) {
                dh[tid + i * NTHR] = sh[tid + i * NTHR];
                dl[tid + i * NTHR] = sl[tid + i * NTHR];
            }
        }
        __syncthreads();

        // ---- mma: 3 passes (AhBh, AhBl, AlBh) over 4 ksteps ----
#pragma unroll
        for (int ks = 0; ks < 4; ++ks) {
            const uint32_t xk = (ks * 32 + kx) ^ swm;
            uint32_t bh[2][4], bl[2][4];
#pragma unroll
            for (int nj = 0; nj < 2; ++nj) {
                ldsm4(bh[nj][0], bh[nj][1], bh[nj][2], bh[nj][3], bHiB + nj * 2048 + xk);
                ldsm4(bl[nj][0], bl[nj][1], bl[nj][2], bl[nj][3], bLoB + nj * 2048 + xk);
            }
#pragma unroll
            for (int mi = 0; mi < 4; ++mi) {
                uint32_t a0, a1, a2, a3;
                ldsm4(a0, a1, a2, a3, aHiB + mi * 2048 + xk);
#pragma unroll
                for (int ni = 0; ni < 4; ++ni) {
                    mma_bf16(acc[mi][ni], a0, a1, a2, a3,
                             bh[ni >> 1][ni & 1], bh[ni >> 1][2 + (ni & 1)]);
                    mma_bf16(acc[mi][ni], a0, a1, a2, a3,
                             bl[ni >> 1][ni & 1], bl[ni >> 1][2 + (ni & 1)]);
                }
                ldsm4(a0, a1, a2, a3, aLoB + mi * 2048 + xk);
#pragma unroll
                for (int ni = 0; ni < 4; ++ni) {
                    mma_bf16(acc[mi][ni], a0, a1, a2, a3,
                             bh[ni >> 1][ni & 1], bh[ni >> 1][2 + (ni & 1)]);
                }
            }
        }
        __syncthreads();   // tiles consumed; safe to overwrite next chunk
    }

    // ---- epilogue: out[row] = sum_n relu(h2 + c2)*w3 + b3 ----
#pragma unroll
    for (int mi = 0; mi < 4; ++mi) {
#pragma unroll
        for (int roff = 0; roff < 2; ++roff) {
            float p = 0.f;
#pragma unroll
            for (int ni = 0; ni < 4; ++ni) {
#pragma unroll
                for (int c = 0; c < 2; ++c) {
                    int n = wn * 32 + ni * 8 + 2 * (lane & 3) + c;
                    float v = acc[mi][ni][roff * 2 + c] + c2s[n];
                    p = fmaf(fmaxf(v, 0.f), w3s[n], p);
                }
            }
            p += __shfl_xor_sync(0xffffffffu, p, 1);
            p += __shfl_xor_sync(0xffffffffu, p, 2);
            if ((lane & 3) == 0)
                red[(wm * 64 + mi * 16 + (lane >> 2) + roff * 8) * 8 + wn] = p;
        }
    }
    __syncthreads();
    if (tid < 128) {
        float s = b3[0];
#pragma unroll
        for (int w = 0; w < 8; ++w) s += red[tid * 8 + w];
        int b = b0 + (tid >> 6);
        int k = k0 + (tid & 63);
        out[b * D_ + k] = s;
    }
}

// ---------------- launch ----------------
extern "C" void kernel_launch(void* const* d_in, const int* in_sizes, int n_in,
                              void* d_out, int out_size) {
    const float* rep   = (const float*)d_in[0];
    const float* emb   = (const float*)d_in[1];
    const float* W1    = (const float*)d_in[2];
    const float* b1    = (const float*)d_in[3];
    const float* g1    = (const float*)d_in[4];
    const float* beta1 = (const float*)d_in[5];
    const float* m1    = (const float*)d_in[6];
    const float* v1    = (const float*)d_in[7];
    const float* W2    = (const float*)d_in[8];
    const float* b2    = (const float*)d_in[9];
    const float* g2    = (const float*)d_in[10];
    const float* beta2 = (const float*)d_in[11];
    const float* m2    = (const float*)d_in[12];
    const float* v2    = (const float*)d_in[13];
    const float* W3    = (const float*)d_in[14];
    const float* b3    = (const float*)d_in[15];
    float* out = (float*)d_out;

    cudaFuncSetAttribute(main_kernel, cudaFuncAttributeMaxDynamicSharedMemorySize, SM_TOTAL);

    prep_base<<<dim3(4, 16), 128>>>(rep, W1, b1, g1, beta1, m1, v1);
    prep_emb <<<D_, H1_>>>(emb, W1, g1, v1);
    prep_wd  <<<(D_ * H1_ / 4) / 256, 256>>>(W1, g1, v1);
    prep_w2  <<<(H1_ * H2_) / 256, 256>>>(W2, b2, g2, beta2, m2, v2);
    main_kernel<<<NCTA, NTHR, SM_TOTAL>>>(rep, W3, b3, out);
}

// round 9
// speedup vs baseline: 1.8927x; 1.0658x over previous
#include <cuda_runtime.h>
#include <cuda_bf16.h>
#include <cstdint>

#define B_   64
#define D_   2048
#define E_   64
#define H1_  512
#define H2_  256
#define EPSF 1e-5f

// ---- main-kernel tiling ----
#define BG    2                      // b per CTA
#define KG    64                     // k per CTA (rows = BG*KG = 128)
#define KCH   64                     // GEMM-K (h) chunk
#define NCH   (H1_ / KCH)            // 8
#define NCTA  ((B_ / BG) * (D_ / KG))    // 1024
#define NTHR  512                    // 16 warps: 2 (m) x 8 (n)

// ---- dynamic SMEM layout (bytes) ----
#define SM_REPS   0                  // 128 floats
#define SM_C2     512                // 256 floats
#define SM_W3     1536               // 256 floats
#define SM_RED    2560               // 128 x 8 floats = 4 KB
#define SM_A0     8192               // 4 x 16 KB  (buf,var)
#define SM_B0     73728              // 4 x 32 KB  (buf,var)
#define SM_TOTAL  204800

#define AOFF(buf, var) (SM_A0 + (((buf) * 2 + (var)) << 14))
#define BOFF(buf, var) (SM_B0 + (((buf) * 2 + (var)) << 15))
#define SW(o) ((o) ^ (((o) >> 3) & 0x70))

// ---- scratch (device globals; no allocation allowed) ----
__device__ float gA [B_ * H1_];     // s1*(rep@W1d + b1) + t1
__device__ float gC [D_ * H1_];     // s1*(emb@W1e)
__device__ float gWd[D_ * H1_];     // s1*W1d
__device__ float gc2[H2_];          // s2*b2 + t2
__device__ __align__(16) unsigned char gBhi[H1_ * H2_ * 2];  // W2' hi, SMEM chunk-image
__device__ __align__(16) unsigned char gBlo[H1_ * H2_ * 2];  // W2' lo, SMEM chunk-image

// ---------------- helpers ----------------
__device__ __forceinline__ uint32_t smem_u32(const void* p) {
    uint32_t a;
    asm("{ .reg .u64 t; cvta.to.shared.u64 t, %1; cvt.u32.u64 %0, t; }" : "=r"(a) : "l"(p));
    return a;
}
__device__ __forceinline__ unsigned short f2bf(float x) {
    unsigned short r;
    asm("cvt.rn.bf16.f32 %0, %1;" : "=h"(r) : "f"(x));
    return r;
}
// packed bf16x2: upper half <- a, lower half <- b
__device__ __forceinline__ uint32_t bf2pk(float a, float b) {
    uint32_t r;
    asm("cvt.rn.bf16x2.f32 %0, %1, %2;" : "=r"(r) : "f"(a), "f"(b));
    return r;
}
__device__ __forceinline__ float pk_lo(uint32_t p) { return __uint_as_float(p << 16); }
__device__ __forceinline__ float pk_hi(uint32_t p) { return __uint_as_float(p & 0xffff0000u); }

__device__ __forceinline__ void ldsm4(uint32_t& r0, uint32_t& r1, uint32_t& r2, uint32_t& r3,
                                      uint32_t addr) {
    asm volatile("ldmatrix.sync.aligned.m8n8.x4.shared.b16 {%0,%1,%2,%3}, [%4];"
                 : "=r"(r0), "=r"(r1), "=r"(r2), "=r"(r3) : "r"(addr));
}
__device__ __forceinline__ void mma_bf16(float* d, uint32_t a0, uint32_t a1, uint32_t a2,
                                         uint32_t a3, uint32_t b0, uint32_t b1) {
    asm volatile(
        "mma.sync.aligned.m16n8k16.row.col.f32.bf16.bf16.f32 "
        "{%0,%1,%2,%3}, {%4,%5,%6,%7}, {%8,%9}, {%0,%1,%2,%3};"
        : "+f"(d[0]), "+f"(d[1]), "+f"(d[2]), "+f"(d[3])
        : "r"(a0), "r"(a1), "r"(a2), "r"(a3), "r"(b0), "r"(b1));
}
__device__ __forceinline__ void cp16(uint32_t saddr, const void* gptr) {
    asm volatile("cp.async.cg.shared.global [%0], [%1], 16;"
                 :: "r"(saddr), "l"(gptr) : "memory");
}
__device__ __forceinline__ void cp_wait_all() {
    asm volatile("cp.async.wait_all;" ::: "memory");
}

// ---------------- prep kernels ----------------

__global__ void prep_base(const float* __restrict__ rep, const float* __restrict__ W1,
                          const float* __restrict__ b1,  const float* __restrict__ g1,
                          const float* __restrict__ beta1, const float* __restrict__ m1,
                          const float* __restrict__ v1) {
    int h  = blockIdx.x * 128 + threadIdx.x;
    int b0 = blockIdx.y * 4;
    const float* r0 = rep + (b0 + 0) * D_;
    const float* r1 = rep + (b0 + 1) * D_;
    const float* r2 = rep + (b0 + 2) * D_;
    const float* r3 = rep + (b0 + 3) * D_;
    float bv = b1[h];
    float a0 = bv, a1 = bv, a2 = bv, a3 = bv;
#pragma unroll 4
    for (int d = 0; d < D_; ++d) {
        float w = W1[d * H1_ + h];
        a0 = fmaf(__ldg(r0 + d), w, a0);
        a1 = fmaf(__ldg(r1 + d), w, a1);
        a2 = fmaf(__ldg(r2 + d), w, a2);
        a3 = fmaf(__ldg(r3 + d), w, a3);
    }
    float s1 = g1[h] * rsqrtf(v1[h] + EPSF);
    float t1 = beta1[h] - m1[h] * s1;
    gA[(b0 + 0) * H1_ + h] = s1 * a0 + t1;
    gA[(b0 + 1) * H1_ + h] = s1 * a1 + t1;
    gA[(b0 + 2) * H1_ + h] = s1 * a2 + t1;
    gA[(b0 + 3) * H1_ + h] = s1 * a3 + t1;
}

__global__ void prep_emb(const float* __restrict__ emb, const float* __restrict__ W1,
                         const float* __restrict__ g1,  const float* __restrict__ v1) {
    int h = threadIdx.x;
    int k = blockIdx.x;
    float s1 = g1[h] * rsqrtf(v1[h] + EPSF);
    const float* ek  = emb + k * E_;
    const float* W1e = W1 + D_ * H1_;
    float acc = 0.f;
#pragma unroll
    for (int e = 0; e < E_; ++e)
        acc = fmaf(ek[e], W1e[e * H1_ + h], acc);
    gC[k * H1_ + h] = s1 * acc;
}

__global__ void prep_wd(const float* __restrict__ W1, const float* __restrict__ g1,
                        const float* __restrict__ v1) {
    int i  = blockIdx.x * blockDim.x + threadIdx.x;
    int h0 = (i * 4) & (H1_ - 1);
    float4 w = ((const float4*)W1)[i];
    float4 o;
    o.x = w.x * (g1[h0 + 0] * rsqrtf(v1[h0 + 0] + EPSF));
    o.y = w.y * (g1[h0 + 1] * rsqrtf(v1[h0 + 1] + EPSF));
    o.z = w.z * (g1[h0 + 2] * rsqrtf(v1[h0 + 2] + EPSF));
    o.w = w.w * (g1[h0 + 3] * rsqrtf(v1[h0 + 3] + EPSF));
    ((float4*)gWd)[i] = o;
}

// W2' = s2*W2 split into bf16 hi/lo, stored as 8 chunk-images:
// chunk c: rows n=0..255, cols k_local=0..63 bf16 (128 B/row), SW128-swizzled.
__global__ void prep_w2(const float* __restrict__ W2, const float* __restrict__ b2,
                        const float* __restrict__ g2, const float* __restrict__ beta2,
                        const float* __restrict__ m2, const float* __restrict__ v2) {
    int idx = blockIdx.x * 256 + threadIdx.x;   // 131072
    int n = idx >> 9;
    int k = idx & 511;
    float s2 = g2[n] * rsqrtf(v2[n] + EPSF);
    float val = W2[k * H2_ + n] * s2;
    unsigned short hb = f2bf(val);
    float hf = __uint_as_float(((uint32_t)hb) << 16);
    unsigned short lb = f2bf(val - hf);
    int off = (k >> 6) * 32768 + SW(n * 128 + (k & 63) * 2);
    *(unsigned short*)(gBhi + off) = hb;
    *(unsigned short*)(gBlo + off) = lb;
    if (blockIdx.x == 0) {
        int o = threadIdx.x;
        float s = g2[o] * rsqrtf(v2[o] + EPSF);
        gc2[o] = s * b2[o] + (beta2[o] - m2[o] * s);
    }
}

// ---------------- main fused pipelined mma.sync kernel ----------------

__device__ __forceinline__ void build_A(unsigned char* smem, const float* reps,
                                        int h0, int buf, int b0, int k0, int tid) {
#pragma unroll
    for (int uu = 0; uu < 4; ++uu) {
        int q   = tid + uu * NTHR;       // 0..2047
        int m   = q >> 4;                // 0..127
        int hq  = q & 15;                // quad within chunk
        int k_i = m & 63;
        int bi  = m >> 6;
        const float4 c4 = *(const float4*)(gC  + (k0 + k_i) * H1_ + h0 + hq * 4);
        const float4 w4 = *(const float4*)(gWd + (k0 + k_i) * H1_ + h0 + hq * 4);
        const float4 a4 = *(const float4*)(gA  + (b0 + bi) * H1_ + h0 + hq * 4);
        float rm = reps[m];
        float f0 = fmaxf(fmaf(-rm, w4.x, a4.x + c4.x), 0.f);
        float f1 = fmaxf(fmaf(-rm, w4.y, a4.y + c4.y), 0.f);
        float f2 = fmaxf(fmaf(-rm, w4.z, a4.z + c4.z), 0.f);
        float f3 = fmaxf(fmaf(-rm, w4.w, a4.w + c4.w), 0.f);
        uint32_t h01 = bf2pk(f1, f0);
        uint32_t h23 = bf2pk(f3, f2);
        float l0 = f0 - pk_lo(h01), l1 = f1 - pk_hi(h01);
        float l2 = f2 - pk_lo(h23), l3 = f3 - pk_hi(h23);
        uint32_t l01 = bf2pk(l1, l0);
        uint32_t l23 = bf2pk(l3, l2);
        int off = SW(m * 128 + hq * 8);
        *(uint2*)(smem + AOFF(buf, 0) + off) = make_uint2(h01, h23);
        *(uint2*)(smem + AOFF(buf, 1) + off) = make_uint2(l01, l23);
    }
}

__device__ __forceinline__ void copy_B_async(uint32_t sbase, int ch, int buf, int tid) {
    const unsigned char* sh = gBhi + ch * 32768;
    const unsigned char* sl = gBlo + ch * 32768;
    const uint32_t dh = sbase + BOFF(buf, 0);
    const uint32_t dl = sbase + BOFF(buf, 1);
#pragma unroll
    for (int i = 0; i < 4; ++i) {
        int off = (tid + i * NTHR) * 16;
        cp16(dh + off, sh + off);
        cp16(dl + off, sl + off);
    }
}

__global__ __launch_bounds__(NTHR, 1)
void main_kernel(const float* __restrict__ rep, const float* __restrict__ W3,
                 const float* __restrict__ b3, float* __restrict__ out) {
    extern __shared__ unsigned char smem[];
    const uint32_t sbase = smem_u32(smem);
    float* reps = (float*)(smem + SM_REPS);
    float* c2s  = (float*)(smem + SM_C2);
    float* w3s  = (float*)(smem + SM_W3);
    float* red  = (float*)(smem + SM_RED);

    const int tid  = threadIdx.x;
    const int lane = tid & 31;
    const int warp = tid >> 5;
    const int wm   = warp >> 3;          // 0..1  -> m block of 64 rows
    const int wn   = warp & 7;           // 0..7  -> n block of 32 cols
    const int bb   = blockIdx.x >> 5;
    const int kb   = blockIdx.x & 31;
    const int b0   = bb * BG;
    const int k0   = kb * KG;

    if (tid < 128) reps[tid] = rep[(b0 + (tid >> 6)) * D_ + k0 + (tid & 63)];
    if (tid < 256) { c2s[tid] = gc2[tid]; w3s[tid] = W3[tid]; }
    __syncthreads();

    // per-lane ldmatrix address components
    const int li   = lane & 7;
    const int tsel = lane >> 3;
    const uint32_t rowoff = (tsel & 1) * 1024 + li * 128;
    const uint32_t kx     = (tsel >> 1) * 16;
    const uint32_t swm    = li << 4;
    const uint32_t aRow = wm * 8192 + rowoff;
    const uint32_t bRow = wn * 4096 + rowoff;

    float acc[4][4][4];
#pragma unroll
    for (int mi = 0; mi < 4; ++mi)
#pragma unroll
        for (int ni = 0; ni < 4; ++ni)
#pragma unroll
            for (int j = 0; j < 4; ++j) acc[mi][ni][j] = 0.f;

    // ---- prologue: stage chunk 0 into buffer 0 ----
    copy_B_async(sbase, 0, 0, tid);
    build_A(smem, reps, 0, 0, b0, k0, tid);
    cp_wait_all();
    __syncthreads();

    for (int ch = 0; ch < NCH; ++ch) {
        const int cur = ch & 1;
        const int nxt = cur ^ 1;
        // stage next chunk (overlaps this chunk's MMA across warps)
        if (ch + 1 < NCH) {
            copy_B_async(sbase, ch + 1, nxt, tid);
            build_A(smem, reps, (ch + 1) * KCH, nxt, b0, k0, tid);
        }
        // ---- mma on current buffers: 3 passes (AhBh, AhBl, AlBh) ----
        const uint32_t aHiB = sbase + AOFF(cur, 0) + aRow;
        const uint32_t aLoB = sbase + AOFF(cur, 1) + aRow;
        const uint32_t bHiB = sbase + BOFF(cur, 0) + bRow;
        const uint32_t bLoB = sbase + BOFF(cur, 1) + bRow;
#pragma unroll
        for (int ks = 0; ks < 4; ++ks) {
            const uint32_t xk = (ks * 32 + kx) ^ swm;
            uint32_t bh[2][4], bl[2][4];
#pragma unroll
            for (int nj = 0; nj < 2; ++nj) {
                ldsm4(bh[nj][0], bh[nj][1], bh[nj][2], bh[nj][3], bHiB + nj * 2048 + xk);
                ldsm4(bl[nj][0], bl[nj][1], bl[nj][2], bl[nj][3], bLoB + nj * 2048 + xk);
            }
#pragma unroll
            for (int mi = 0; mi < 4; ++mi) {
                uint32_t a0, a1, a2, a3;
                ldsm4(a0, a1, a2, a3, aHiB + mi * 2048 + xk);
#pragma unroll
                for (int ni = 0; ni < 4; ++ni) {
                    mma_bf16(acc[mi][ni], a0, a1, a2, a3,
                             bh[ni >> 1][ni & 1], bh[ni >> 1][2 + (ni & 1)]);
                    mma_bf16(acc[mi][ni], a0, a1, a2, a3,
                             bl[ni >> 1][ni & 1], bl[ni >> 1][2 + (ni & 1)]);
                }
                ldsm4(a0, a1, a2, a3, aLoB + mi * 2048 + xk);
#pragma unroll
                for (int ni = 0; ni < 4; ++ni) {
                    mma_bf16(acc[mi][ni], a0, a1, a2, a3,
                             bh[ni >> 1][ni & 1], bh[ni >> 1][2 + (ni & 1)]);
                }
            }
        }
        cp_wait_all();
        __syncthreads();   // next buffers fully staged; current consumed
    }

    // ---- epilogue: out[row] = sum_n relu(h2 + c2)*w3 + b3 ----
#pragma unroll
    for (int mi = 0; mi < 4; ++mi) {
#pragma unroll
        for (int roff = 0; roff < 2; ++roff) {
            float p = 0.f;
#pragma unroll
            for (int ni = 0; ni < 4; ++ni) {
#pragma unroll
                for (int c = 0; c < 2; ++c) {
                    int n = wn * 32 + ni * 8 + 2 * (lane & 3) + c;
                    float v = acc[mi][ni][roff * 2 + c] + c2s[n];
                    p = fmaf(fmaxf(v, 0.f), w3s[n], p);
                }
            }
            p += __shfl_xor_sync(0xffffffffu, p, 1);
            p += __shfl_xor_sync(0xffffffffu, p, 2);
            if ((lane & 3) == 0)
                red[(wm * 64 + mi * 16 + (lane >> 2) + roff * 8) * 8 + wn] = p;
        }
    }
    __syncthreads();
    if (tid < 128) {
        float s = b3[0];
#pragma unroll
        for (int w = 0; w < 8; ++w) s += red[tid * 8 + w];
        int b = b0 + (tid >> 6);
        int k = k0 + (tid & 63);
        out[b * D_ + k] = s;
    }
}

// ---------------- launch ----------------
extern "C" void kernel_launch(void* const* d_in, const int* in_sizes, int n_in,
                              void* d_out, int out_size) {
    const float* rep   = (const float*)d_in[0];
    const float* emb   = (const float*)d_in[1];
    const float* W1    = (const float*)d_in[2];
    const float* b1    = (const float*)d_in[3];
    const float* g1    = (const float*)d_in[4];
    const float* beta1 = (const float*)d_in[5];
    const float* m1    = (const float*)d_in[6];
    const float* v1    = (const float*)d_in[7];
    const float* W2    = (const float*)d_in[8];
    const float* b2    = (const float*)d_in[9];
    const float* g2    = (const float*)d_in[10];
    const float* beta2 = (const float*)d_in[11];
    const float* m2    = (const float*)d_in[12];
    const float* v2    = (const float*)d_in[13];
    const float* W3    = (const float*)d_in[14];
    const float* b3    = (const float*)d_in[15];
    float* out = (float*)d_out;

    cudaFuncSetAttribute(main_kernel, cudaFuncAttributeMaxDynamicSharedMemorySize, SM_TOTAL);

    prep_base<<<dim3(4, 16), 128>>>(rep, W1, b1, g1, beta1, m1, v1);
    prep_emb <<<D_, H1_>>>(emb, W1, g1, v1);
    prep_wd  <<<(D_ * H1_ / 4) / 256, 256>>>(W1, g1, v1);
    prep_w2  <<<(H1_ * H2_) / 256, 256>>>(W2, b2, g2, beta2, m2, v2);
    main_kernel<<<NCTA, NTHR, SM_TOTAL>>>(rep, W3, b3, out);
}

// round 12
// speedup vs baseline: 2.9711x; 1.5698x over previous
#include <cuda_runtime.h>
#include <cuda_fp16.h>
#include <cstdint>

#define B_   64
#define D_   2048
#define E_   64
#define H1_  512
#define H2_  256
#define EPSF 1e-5f

// ---- main-kernel tiling ----
#define BG    2                      // b per CTA
#define KG    64                     // k per CTA (rows = BG*KG = 128)
#define KCH   64                     // GEMM-K (h) chunk
#define NCH   (H1_ / KCH)            // 8
#define NCTA  ((B_ / BG) * (D_ / KG))    // 1024
#define NTHR  512                    // 16 warps: 2 (m) x 8 (n)

// ---- dynamic SMEM layout (bytes) ----
#define SM_REPS   0                  // 128 floats
#define SM_C2     512                // 256 floats
#define SM_W3     1536               // 256 floats
#define SM_RED    2560               // 128 x 8 floats = 4 KB
#define SM_A0     8192               // 2 x 16 KB (buf)
#define SM_B0     40960              // 2 x 32 KB (buf)
#define SM_TOTAL  106496

#define AOFF(buf) (SM_A0 + ((buf) << 14))
#define BOFF(buf) (SM_B0 + ((buf) << 15))
#define SW(o) ((o) ^ (((o) >> 3) & 0x70))

// ---- scratch (device globals; no allocation allowed) ----
__device__ float gA [B_ * H1_];     // s1*(rep@W1d + b1) + t1
__device__ float gC [D_ * H1_];     // s1*(emb@W1e)
__device__ float gWd[D_ * H1_];     // s1*W1d
__device__ float gc2[H2_];          // s2*b2 + t2
__device__ __align__(16) unsigned char gBimg[H1_ * H2_ * 2];  // W2' fp16 chunk-images

// ---------------- helpers ----------------
__device__ __forceinline__ uint32_t smem_u32(const void* p) {
    uint32_t a;
    asm("{ .reg .u64 t; cvta.to.shared.u64 t, %1; cvt.u32.u64 %0, t; }" : "=r"(a) : "l"(p));
    return a;
}
// packed f16x2: low half <- a, high half <- b
__device__ __forceinline__ uint32_t h2pk(float a, float b) {
    __half2 h = __floats2half2_rn(a, b);
    return *(uint32_t*)&h;
}
__device__ __forceinline__ void ldsm4(uint32_t& r0, uint32_t& r1, uint32_t& r2, uint32_t& r3,
                                      uint32_t addr) {
    asm volatile("ldmatrix.sync.aligned.m8n8.x4.shared.b16 {%0,%1,%2,%3}, [%4];"
                 : "=r"(r0), "=r"(r1), "=r"(r2), "=r"(r3) : "r"(addr));
}
__device__ __forceinline__ void mma_f16(float* d, uint32_t a0, uint32_t a1, uint32_t a2,
                                        uint32_t a3, uint32_t b0, uint32_t b1) {
    asm volatile(
        "mma.sync.aligned.m16n8k16.row.col.f32.f16.f16.f32 "
        "{%0,%1,%2,%3}, {%4,%5,%6,%7}, {%8,%9}, {%0,%1,%2,%3};"
        : "+f"(d[0]), "+f"(d[1]), "+f"(d[2]), "+f"(d[3])
        : "r"(a0), "r"(a1), "r"(a2), "r"(a3), "r"(b0), "r"(b1));
}
__device__ __forceinline__ void cp16(uint32_t saddr, const void* gptr) {
    asm volatile("cp.async.cg.shared.global [%0], [%1], 16;"
                 :: "r"(saddr), "l"(gptr) : "memory");
}
__device__ __forceinline__ void cp_wait_all() {
    asm volatile("cp.async.wait_all;" ::: "memory");
}

// ---------------- prep kernels ----------------

__global__ void prep_base(const float* __restrict__ rep, const float* __restrict__ W1,
                          const float* __restrict__ b1,  const float* __restrict__ g1,
                          const float* __restrict__ beta1, const float* __restrict__ m1,
                          const float* __restrict__ v1) {
    int h  = blockIdx.x * 128 + threadIdx.x;
    int b0 = blockIdx.y * 4;
    const float* r0 = rep + (b0 + 0) * D_;
    const float* r1 = rep + (b0 + 1) * D_;
    const float* r2 = rep + (b0 + 2) * D_;
    const float* r3 = rep + (b0 + 3) * D_;
    float bv = b1[h];
    float a0 = bv, a1 = bv, a2 = bv, a3 = bv;
#pragma unroll 4
    for (int d = 0; d < D_; ++d) {
        float w = W1[d * H1_ + h];
        a0 = fmaf(__ldg(r0 + d), w, a0);
        a1 = fmaf(__ldg(r1 + d), w, a1);
        a2 = fmaf(__ldg(r2 + d), w, a2);
        a3 = fmaf(__ldg(r3 + d), w, a3);
    }
    float s1 = g1[h] * rsqrtf(v1[h] + EPSF);
    float t1 = beta1[h] - m1[h] * s1;
    gA[(b0 + 0) * H1_ + h] = s1 * a0 + t1;
    gA[(b0 + 1) * H1_ + h] = s1 * a1 + t1;
    gA[(b0 + 2) * H1_ + h] = s1 * a2 + t1;
    gA[(b0 + 3) * H1_ + h] = s1 * a3 + t1;
}

__global__ void prep_emb(const float* __restrict__ emb, const float* __restrict__ W1,
                         const float* __restrict__ g1,  const float* __restrict__ v1) {
    int h = threadIdx.x;
    int k = blockIdx.x;
    float s1 = g1[h] * rsqrtf(v1[h] + EPSF);
    const float* ek  = emb + k * E_;
    const float* W1e = W1 + D_ * H1_;
    float acc = 0.f;
#pragma unroll
    for (int e = 0; e < E_; ++e)
        acc = fmaf(ek[e], W1e[e * H1_ + h], acc);
    gC[k * H1_ + h] = s1 * acc;
}

__global__ void prep_wd(const float* __restrict__ W1, const float* __restrict__ g1,
                        const float* __restrict__ v1) {
    int i  = blockIdx.x * blockDim.x + threadIdx.x;
    int h0 = (i * 4) & (H1_ - 1);
    float4 w = ((const float4*)W1)[i];
    float4 o;
    o.x = w.x * (g1[h0 + 0] * rsqrtf(v1[h0 + 0] + EPSF));
    o.y = w.y * (g1[h0 + 1] * rsqrtf(v1[h0 + 1] + EPSF));
    o.z = w.z * (g1[h0 + 2] * rsqrtf(v1[h0 + 2] + EPSF));
    o.w = w.w * (g1[h0 + 3] * rsqrtf(v1[h0 + 3] + EPSF));
    ((float4*)gWd)[i] = o;
}

// W2' = s2*W2 as fp16, stored as 8 chunk-images:
// chunk c: rows n=0..255, cols k_local=0..63 fp16 (128 B/row), SW128-swizzled.
__global__ void prep_w2(const float* __restrict__ W2, const float* __restrict__ b2,
                        const float* __restrict__ g2, const float* __restrict__ beta2,
                        const float* __restrict__ m2, const float* __restrict__ v2) {
    int idx = blockIdx.x * 256 + threadIdx.x;   // 131072
    int n = idx >> 9;
    int k = idx & 511;
    float s2 = g2[n] * rsqrtf(v2[n] + EPSF);
    float val = W2[k * H2_ + n] * s2;
    __half hv = __float2half_rn(val);
    int off = (k >> 6) * 32768 + SW(n * 128 + (k & 63) * 2);
    *(__half*)(gBimg + off) = hv;
    if (blockIdx.x == 0) {
        int o = threadIdx.x;
        float s = g2[o] * rsqrtf(v2[o] + EPSF);
        gc2[o] = s * b2[o] + (beta2[o] - m2[o] * s);
    }
}

// ---------------- main fused pipelined mma.sync kernel ----------------

__device__ __forceinline__ void build_A(unsigned char* smem, const float* reps,
                                        int h0, int buf, int b0, int k0, int tid) {
#pragma unroll
    for (int uu = 0; uu < 4; ++uu) {
        int q   = tid + uu * NTHR;       // 0..2047
        int m   = q >> 4;                // 0..127
        int hq  = q & 15;                // quad within chunk
        int k_i = m & 63;
        int bi  = m >> 6;
        const float4 c4 = *(const float4*)(gC  + (k0 + k_i) * H1_ + h0 + hq * 4);
        const float4 w4 = *(const float4*)(gWd + (k0 + k_i) * H1_ + h0 + hq * 4);
        const float4 a4 = *(const float4*)(gA  + (b0 + bi) * H1_ + h0 + hq * 4);
        float rm = reps[m];
        float f0 = fmaxf(fmaf(-rm, w4.x, a4.x + c4.x), 0.f);
        float f1 = fmaxf(fmaf(-rm, w4.y, a4.y + c4.y), 0.f);
        float f2 = fmaxf(fmaf(-rm, w4.z, a4.z + c4.z), 0.f);
        float f3 = fmaxf(fmaf(-rm, w4.w, a4.w + c4.w), 0.f);
        uint32_t h01 = h2pk(f0, f1);
        uint32_t h23 = h2pk(f2, f3);
        int off = SW(m * 128 + hq * 8);
        *(uint2*)(smem + AOFF(buf) + off) = make_uint2(h01, h23);
    }
}

__device__ __forceinline__ void copy_B_async(uint32_t sbase, int ch, int buf, int tid) {
    const unsigned char* src = gBimg + ch * 32768;
    const uint32_t dst = sbase + BOFF(buf);
#pragma unroll
    for (int i = 0; i < 4; ++i) {
        int off = (tid + i * NTHR) * 16;
        cp16(dst + off, src + off);
    }
}

__global__ __launch_bounds__(NTHR, 1)
void main_kernel(const float* __restrict__ rep, const float* __restrict__ W3,
                 const float* __restrict__ b3, float* __restrict__ out) {
    extern __shared__ unsigned char smem[];
    const uint32_t sbase = smem_u32(smem);
    float* reps = (float*)(smem + SM_REPS);
    float* c2s  = (float*)(smem + SM_C2);
    float* w3s  = (float*)(smem + SM_W3);
    float* red  = (float*)(smem + SM_RED);

    const int tid  = threadIdx.x;
    const int lane = tid & 31;
    const int warp = tid >> 5;
    const int wm   = warp >> 3;          // 0..1  -> m block of 64 rows
    const int wn   = warp & 7;           // 0..7  -> n block of 32 cols
    const int bb   = blockIdx.x >> 5;
    const int kb   = blockIdx.x & 31;
    const int b0   = bb * BG;
    const int k0   = kb * KG;

    if (tid < 128) reps[tid] = rep[(b0 + (tid >> 6)) * D_ + k0 + (tid & 63)];
    if (tid < 256) { c2s[tid] = gc2[tid]; w3s[tid] = W3[tid]; }
    __syncthreads();

    // per-lane ldmatrix address components
    const int li   = lane & 7;
    const int tsel = lane >> 3;
    const uint32_t rowoff = (tsel & 1) * 1024 + li * 128;
    const uint32_t kx     = (tsel >> 1) * 16;
    const uint32_t swm    = li << 4;
    const uint32_t aRow = wm * 8192 + rowoff;
    const uint32_t bRow = wn * 4096 + rowoff;

    float acc[4][4][4];
#pragma unroll
    for (int mi = 0; mi < 4; ++mi)
#pragma unroll
        for (int ni = 0; ni < 4; ++ni)
#pragma unroll
            for (int j = 0; j < 4; ++j) acc[mi][ni][j] = 0.f;

    // ---- prologue: stage chunk 0 into buffer 0 ----
    copy_B_async(sbase, 0, 0, tid);
    build_A(smem, reps, 0, 0, b0, k0, tid);
    cp_wait_all();
    __syncthreads();

    for (int ch = 0; ch < NCH; ++ch) {
        const int cur = ch & 1;
        const int nxt = cur ^ 1;
        // stage next chunk (overlaps this chunk's MMA across warps)
        if (ch + 1 < NCH) {
            copy_B_async(sbase, ch + 1, nxt, tid);
            build_A(smem, reps, (ch + 1) * KCH, nxt, b0, k0, tid);
        }
        // ---- mma on current buffers (single fp16 pass) ----
        const uint32_t aB = sbase + AOFF(cur) + aRow;
        const uint32_t bB = sbase + BOFF(cur) + bRow;
#pragma unroll
        for (int ks = 0; ks < 4; ++ks) {
            const uint32_t xk = (ks * 32 + kx) ^ swm;
            uint32_t bh[2][4];
#pragma unroll
            for (int nj = 0; nj < 2; ++nj)
                ldsm4(bh[nj][0], bh[nj][1], bh[nj][2], bh[nj][3], bB + nj * 2048 + xk);
#pragma unroll
            for (int mi = 0; mi < 4; ++mi) {
                uint32_t a0, a1, a2, a3;
                ldsm4(a0, a1, a2, a3, aB + mi * 2048 + xk);
#pragma unroll
                for (int ni = 0; ni < 4; ++ni)
                    mma_f16(acc[mi][ni], a0, a1, a2, a3,
                            bh[ni >> 1][ni & 1], bh[ni >> 1][2 + (ni & 1)]);
            }
        }
        cp_wait_all();
        __syncthreads();   // next buffers fully staged; current consumed
    }

    // ---- epilogue: out[row] = sum_n relu(h2 + c2)*w3 + b3 ----
#pragma unroll
    for (int mi = 0; mi < 4; ++mi) {
#pragma unroll
        for (int roff = 0; roff < 2; ++roff) {
            float p = 0.f;
#pragma unroll
            for (int ni = 0; ni < 4; ++ni) {
#pragma unroll
                for (int c = 0; c < 2; ++c) {
                    int n = wn * 32 + ni * 8 + 2 * (lane & 3) + c;
                    float v = acc[mi][ni][roff * 2 + c] + c2s[n];
                    p = fmaf(fmaxf(v, 0.f), w3s[n], p);
                }
            }
            p += __shfl_xor_sync(0xffffffffu, p, 1);
            p += __shfl_xor_sync(0xffffffffu, p, 2);
            if ((lane & 3) == 0)
                red[(wm * 64 + mi * 16 + (lane >> 2) + roff * 8) * 8 + wn] = p;
        }
    }
    __syncthreads();
    if (tid < 128) {
        float s = b3[0];
#pragma unroll
        for (int w = 0; w < 8; ++w) s += red[tid * 8 + w];
        int b = b0 + (tid >> 6);
        int k = k0 + (tid & 63);
        out[b * D_ + k] = s;
    }
}

// ---------------- launch ----------------
extern "C" void kernel_launch(void* const* d_in, const int* in_sizes, int n_in,
                              void* d_out, int out_size) {
    const float* rep   = (const float*)d_in[0];
    const float* emb   = (const float*)d_in[1];
    const float* W1    = (const float*)d_in[2];
    const float* b1    = (const float*)d_in[3];
    const float* g1    = (const float*)d_in[4];
    const float* beta1 = (const float*)d_in[5];
    const float* m1    = (const float*)d_in[6];
    const float* v1    = (const float*)d_in[7];
    const float* W2    = (const float*)d_in[8];
    const float* b2    = (const float*)d_in[9];
    const float* g2    = (const float*)d_in[10];
    const float* beta2 = (const float*)d_in[11];
    const float* m2    = (const float*)d_in[12];
    const float* v2    = (const float*)d_in[13];
    const float* W3    = (const float*)d_in[14];
    const float* b3    = (const float*)d_in[15];
    float* out = (float*)d_out;

    cudaFuncSetAttribute(main_kernel, cudaFuncAttributeMaxDynamicSharedMemorySize, SM_TOTAL);

    prep_base<<<dim3(4, 16), 128>>>(rep, W1, b1, g1, beta1, m1, v1);
    prep_emb <<<D_, H1_>>>(emb, W1, g1, v1);
    prep_wd  <<<(D_ * H1_ / 4) / 256, 256>>>(W1, g1, v1);
    prep_w2  <<<(H1_ * H2_) / 256, 256>>>(W2, b2, g2, beta2, m2, v2);
    main_kernel<<<NCTA, NTHR, SM_TOTAL>>>(rep, W3, b3, out);
}

// round 17
// speedup vs baseline: 3.2688x; 1.1002x over previous
#include <cuda_runtime.h>
#include <cuda_fp16.h>
#include <cstdint>

#define B_   64
#define D_   2048
#define E_   64
#define H1_  512
#define H2_  256
#define EPSF 1e-5f

// ---- main-kernel tiling ----
#define BG    2                      // b per CTA
#define KG    64                     // k per CTA (rows = BG*KG = 128)
#define KCH   64                     // GEMM-K (h) chunk
#define NCH   (H1_ / KCH)            // 8
#define NCTA  ((B_ / BG) * (D_ / KG))    // 1024
#define NTHR  512                    // 16 warps: 2 (m) x 8 (n)

// ---- dynamic SMEM layout (bytes) ----
#define SM_REPS   0                  // 128 floats
#define SM_C2     512                // 256 floats
#define SM_W3     1536               // 256 floats
#define SM_RED    2560               // 128 x 8 floats = 4 KB
#define SM_A0     8192               // 2 x 16 KB (buf)
#define SM_B0     40960              // 2 x 32 KB (buf)
#define SM_TOTAL  106496

#define AOFF(buf) (SM_A0 + ((buf) << 14))
#define BOFF(buf) (SM_B0 + ((buf) << 15))
#define SW(o) ((o) ^ (((o) >> 3) & 0x70))

// ---- scratch (device globals; no allocation allowed) ----
__device__ float gC [D_ * H1_];                         // s1*(emb@W1e)  (fp32 intermediate)
__device__ float gc2[H2_];                              // s2*b2 + t2
__device__ __align__(16) __half gAh[B_ * H1_];          // fp16: s1*(rep@W1d+b1)+t1
__device__ __align__(16) unsigned char gCW [D_ * 2048]; // per (k, hquad): {c01,c23,w01,w23} fp16
__device__ __align__(16) unsigned char gBimg[H1_ * H2_ * 2];  // W2' fp16 chunk-images

// ---------------- helpers ----------------
__device__ __forceinline__ uint32_t smem_u32(const void* p) {
    uint32_t a;
    asm("{ .reg .u64 t; cvta.to.shared.u64 t, %1; cvt.u32.u64 %0, t; }" : "=r"(a) : "l"(p));
    return a;
}
__device__ __forceinline__ uint32_t h2pk(float a, float b) {
    __half2 h = __floats2half2_rn(a, b);
    return *(uint32_t*)&h;
}
__device__ __forceinline__ __half2 u2h(uint32_t u) { return *(__half2*)&u; }
__device__ __forceinline__ uint32_t h2u(__half2 h) { return *(uint32_t*)&h; }

__device__ __forceinline__ void ldsm4(uint32_t& r0, uint32_t& r1, uint32_t& r2, uint32_t& r3,
                                      uint32_t addr) {
    asm volatile("ldmatrix.sync.aligned.m8n8.x4.shared.b16 {%0,%1,%2,%3}, [%4];"
                 : "=r"(r0), "=r"(r1), "=r"(r2), "=r"(r3) : "r"(addr));
}
__device__ __forceinline__ void mma_f16(float* d, uint32_t a0, uint32_t a1, uint32_t a2,
                                        uint32_t a3, uint32_t b0, uint32_t b1) {
    asm volatile(
        "mma.sync.aligned.m16n8k16.row.col.f32.f16.f16.f32 "
        "{%0,%1,%2,%3}, {%4,%5,%6,%7}, {%8,%9}, {%0,%1,%2,%3};"
        : "+f"(d[0]), "+f"(d[1]), "+f"(d[2]), "+f"(d[3])
        : "r"(a0), "r"(a1), "r"(a2), "r"(a3), "r"(b0), "r"(b1));
}
__device__ __forceinline__ void cp16(uint32_t saddr, const void* gptr) {
    asm volatile("cp.async.cg.shared.global [%0], [%1], 16;"
                 :: "r"(saddr), "l"(gptr) : "memory");
}
__device__ __forceinline__ void cp_wait_all() {
    asm volatile("cp.async.wait_all;" ::: "memory");
}

// ---------------- prep kernels ----------------

// gAh[b,h] = fp16( s1[h]*(rep[b,:]@W1d[:,h] + b1[h]) + t1[h] )
__global__ void prep_base(const float* __restrict__ rep, const float* __restrict__ W1,
                          const float* __restrict__ b1,  const float* __restrict__ g1,
                          const float* __restrict__ beta1, const float* __restrict__ m1,
                          const float* __restrict__ v1) {
    int h  = blockIdx.x * 128 + threadIdx.x;
    int b0 = blockIdx.y * 4;
    const float* r0 = rep + (b0 + 0) * D_;
    const float* r1 = rep + (b0 + 1) * D_;
    const float* r2 = rep + (b0 + 2) * D_;
    const float* r3 = rep + (b0 + 3) * D_;
    float bv = b1[h];
    float a0 = bv, a1 = bv, a2 = bv, a3 = bv;
#pragma unroll 4
    for (int d = 0; d < D_; ++d) {
        float w = W1[d * H1_ + h];
        a0 = fmaf(__ldg(r0 + d), w, a0);
        a1 = fmaf(__ldg(r1 + d), w, a1);
        a2 = fmaf(__ldg(r2 + d), w, a2);
        a3 = fmaf(__ldg(r3 + d), w, a3);
    }
    float s1 = g1[h] * rsqrtf(v1[h] + EPSF);
    float t1 = beta1[h] - m1[h] * s1;
    gAh[(b0 + 0) * H1_ + h] = __float2half_rn(s1 * a0 + t1);
    gAh[(b0 + 1) * H1_ + h] = __float2half_rn(s1 * a1 + t1);
    gAh[(b0 + 2) * H1_ + h] = __float2half_rn(s1 * a2 + t1);
    gAh[(b0 + 3) * H1_ + h] = __float2half_rn(s1 * a3 + t1);
}

// gC[k,h] = s1[h]*(emb[k,:]@W1e[:,h])   (fp32 intermediate)
__global__ void prep_emb(const float* __restrict__ emb, const float* __restrict__ W1,
                         const float* __restrict__ g1,  const float* __restrict__ v1) {
    int h = threadIdx.x;
    int k = blockIdx.x;
    float s1 = g1[h] * rsqrtf(v1[h] + EPSF);
    const float* ek  = emb + k * E_;
    const float* W1e = W1 + D_ * H1_;
    float acc = 0.f;
#pragma unroll
    for (int e = 0; e < E_; ++e)
        acc = fmaf(ek[e], W1e[e * H1_ + h], acc);
    gC[k * H1_ + h] = s1 * acc;
}

// gCW[k][hquad] = {c01,c23,w01,w23} fp16  (one uint4 per 4 h)
__global__ void prep_cw(const float* __restrict__ W1, const float* __restrict__ g1,
                        const float* __restrict__ v1) {
    int idx = blockIdx.x * 256 + threadIdx.x;   // D_*H1_/4 = 262144
    int k  = idx >> 7;
    int hq = idx & 127;
    int h0 = hq * 4;
    float4 c4 = *(const float4*)(gC + k * H1_ + h0);
    float4 w4 = *(const float4*)(W1 + k * H1_ + h0);
    float s0 = g1[h0 + 0] * rsqrtf(v1[h0 + 0] + EPSF);
    float s1 = g1[h0 + 1] * rsqrtf(v1[h0 + 1] + EPSF);
    float s2 = g1[h0 + 2] * rsqrtf(v1[h0 + 2] + EPSF);
    float s3 = g1[h0 + 3] * rsqrtf(v1[h0 + 3] + EPSF);
    uint4 o;
    o.x = h2pk(c4.x, c4.y);
    o.y = h2pk(c4.z, c4.w);
    o.z = h2pk(w4.x * s0, w4.y * s1);
    o.w = h2pk(w4.z * s2, w4.w * s3);
    *(uint4*)(gCW + k * 2048 + hq * 16) = o;
}

// W2' = s2*W2 as fp16, stored as 8 chunk-images (SW128-swizzled, 128 B/row)
__global__ void prep_w2(const float* __restrict__ W2, const float* __restrict__ b2,
                        const float* __restrict__ g2, const float* __restrict__ beta2,
                        const float* __restrict__ m2, const float* __restrict__ v2) {
    int idx = blockIdx.x * 256 + threadIdx.x;   // 131072
    int n = idx >> 9;
    int k = idx & 511;
    float s2 = g2[n] * rsqrtf(v2[n] + EPSF);
    float val = W2[k * H2_ + n] * s2;
    __half hv = __float2half_rn(val);
    int off = (k >> 6) * 32768 + SW(n * 128 + (k & 63) * 2);
    *(__half*)(gBimg + off) = hv;
    if (blockIdx.x == 0) {
        int o = threadIdx.x;
        float s = g2[o] * rsqrtf(v2[o] + EPSF);
        gc2[o] = s * b2[o] + (beta2[o] - m2[o] * s);
    }
}

// ---------------- main fused pipelined mma.sync kernel ----------------

__device__ __forceinline__ void copy_B_async(uint32_t sbase, int ch, int buf, int tid) {
    const unsigned char* src = gBimg + ch * 32768;
    const uint32_t dst = sbase + BOFF(buf);
#pragma unroll
    for (int i = 0; i < 4; ++i) {
        int off = (tid + i * NTHR) * 16;
        cp16(dst + off, src + off);
    }
}

__global__ __launch_bounds__(NTHR, 1)
void main_kernel(const float* __restrict__ rep, const float* __restrict__ W3,
                 const float* __restrict__ b3, float* __restrict__ out) {
    extern __shared__ unsigned char smem[];
    const uint32_t sbase = smem_u32(smem);
    float* reps = (float*)(smem + SM_REPS);
    float* c2s  = (float*)(smem + SM_C2);
    float* w3s  = (float*)(smem + SM_W3);
    float* red  = (float*)(smem + SM_RED);

    const int tid  = threadIdx.x;
    const int lane = tid & 31;
    const int warp = tid >> 5;
    const int wm   = warp >> 3;          // 0..1  -> m block of 64 rows
    const int wn   = warp & 7;           // 0..7  -> n block of 32 cols
    const int bb   = blockIdx.x >> 5;
    const int kb   = blockIdx.x & 31;
    const int b0   = bb * BG;
    const int k0   = kb * KG;

    if (tid < 128) reps[tid] = rep[(b0 + (tid >> 6)) * D_ + k0 + (tid & 63)];
    if (tid < 256) { c2s[tid] = gc2[tid]; w3s[tid] = W3[tid]; }
    __syncthreads();

    // per-thread build indexing: t4 = row base, hq = quad within chunk
    const int t4 = tid >> 4;            // 0..31
    const int hq = tid & 15;            // 0..15

    // per-lane ldmatrix address components
    const int li   = lane & 7;
    const int tsel = lane >> 3;
    const uint32_t rowoff = (tsel & 1) * 1024 + li * 128;
    const uint32_t kx     = (tsel >> 1) * 16;
    const uint32_t swm    = li << 4;
    const uint32_t aRow = wm * 8192 + rowoff;
    const uint32_t bRow = wn * 4096 + rowoff;

    float acc[4][4][4];
#pragma unroll
    for (int mi = 0; mi < 4; ++mi)
#pragma unroll
        for (int ni = 0; ni < 4; ++ni)
#pragma unroll
            for (int j = 0; j < 4; ++j) acc[mi][ni][j] = 0.f;

    uint4 cwr[4];
    uint2 ar[4];

    // fetch chunk ch's A inputs into registers (LDGs; no use until store_A)
    auto fetch_A = [&](int ch) {
#pragma unroll
        for (int uu = 0; uu < 4; ++uu) {
            int k_i = t4 + (uu & 1) * 32;
            int bi  = uu >> 1;
            cwr[uu] = *(const uint4*)(gCW + (k0 + k_i) * 2048 + ch * 256 + hq * 16);
            ar[uu]  = *(const uint2*)(gAh + (b0 + bi) * H1_ + ch * KCH + hq * 4);
        }
    };
    // convert + STS into buffer buf
    auto store_A = [&](int buf) {
        const __half2 z = __floats2half2_rn(0.f, 0.f);
#pragma unroll
        for (int uu = 0; uu < 4; ++uu) {
            int k_i = t4 + (uu & 1) * 32;
            int bi  = uu >> 1;
            int m   = bi * 64 + k_i;
            __half2 nrm = __float2half2_rn(-reps[m]);
            __half2 r01 = __hmax2(__hfma2(nrm, u2h(cwr[uu].z),
                                  __hadd2(u2h(ar[uu].x), u2h(cwr[uu].x))), z);
            __half2 r23 = __hmax2(__hfma2(nrm, u2h(cwr[uu].w),
                                  __hadd2(u2h(ar[uu].y), u2h(cwr[uu].y))), z);
            int off = SW(m * 128 + hq * 8);
            *(uint2*)(smem + AOFF(buf) + off) = make_uint2(h2u(r01), h2u(r23));
        }
    };

    // ---- prologue: stage chunk 0 into buffer 0 ----
    fetch_A(0);
    copy_B_async(sbase, 0, 0, tid);
    store_A(0);
    cp_wait_all();
    __syncthreads();

    for (int ch = 0; ch < NCH; ++ch) {
        const int cur = ch & 1;
        const int nxt = cur ^ 1;
        // issue next chunk's loads BEFORE the mma section (latency hides under HMMA)
        if (ch + 1 < NCH) {
            fetch_A(ch + 1);
            copy_B_async(sbase, ch + 1, nxt, tid);
        }
        // ---- mma on current buffers (single fp16 pass) ----
        const uint32_t aB = sbase + AOFF(cur) + aRow;
        const uint32_t bB = sbase + BOFF(cur) + bRow;
#pragma unroll
        for (int ks = 0; ks < 4; ++ks) {
            const uint32_t xk = (ks * 32 + kx) ^ swm;
            uint32_t bh[2][4];
#pragma unroll
            for (int nj = 0; nj < 2; ++nj)
                ldsm4(bh[nj][0], bh[nj][1], bh[nj][2], bh[nj][3], bB + nj * 2048 + xk);
#pragma unroll
            for (int mi = 0; mi < 4; ++mi) {
                uint32_t a0, a1, a2, a3;
                ldsm4(a0, a1, a2, a3, aB + mi * 2048 + xk);
#pragma unroll
                for (int ni = 0; ni < 4; ++ni)
                    mma_f16(acc[mi][ni], a0, a1, a2, a3,
                            bh[ni >> 1][ni & 1], bh[ni >> 1][2 + (ni & 1)]);
            }
        }
        // convert + store next A tile after the mma (LDGs have landed by now)
        if (ch + 1 < NCH) store_A(nxt);
        cp_wait_all();
        __syncthreads();
    }

    // ---- epilogue: out[row] = sum_n relu(h2 + c2)*w3 + b3 ----
#pragma unroll
    for (int mi = 0; mi < 4; ++mi) {
#pragma unroll
        for (int roff = 0; roff < 2; ++roff) {
            float p = 0.f;
#pragma unroll
            for (int ni = 0; ni < 4; ++ni) {
#pragma unroll
                for (int c = 0; c < 2; ++c) {
                    int n = wn * 32 + ni * 8 + 2 * (lane & 3) + c;
                    float v = acc[mi][ni][roff * 2 + c] + c2s[n];
                    p = fmaf(fmaxf(v, 0.f), w3s[n], p);
                }
            }
            p += __shfl_xor_sync(0xffffffffu, p, 1);
            p += __shfl_xor_sync(0xffffffffu, p, 2);
            if ((lane & 3) == 0)
                red[(wm * 64 + mi * 16 + (lane >> 2) + roff * 8) * 8 + wn] = p;
        }
    }
    __syncthreads();
    if (tid < 128) {
        float s = b3[0];
#pragma unroll
        for (int w = 0; w < 8; ++w) s += red[tid * 8 + w];
        int b = b0 + (tid >> 6);
        int k = k0 + (tid & 63);
        out[b * D_ + k] = s;
    }
}

// ---------------- launch ----------------
extern "C" void kernel_launch(void* const* d_in, const int* in_sizes, int n_in,
                              void* d_out, int out_size) {
    const float* rep   = (const float*)d_in[0];
    const float* emb   = (const float*)d_in[1];
    const float* W1    = (const float*)d_in[2];
    const float* b1    = (const float*)d_in[3];
    const float* g1    = (const float*)d_in[4];
    const float* beta1 = (const float*)d_in[5];
    const float* m1    = (const float*)d_in[6];
    const float* v1    = (const float*)d_in[7];
    const float* W2    = (const float*)d_in[8];
    const float* b2    = (const float*)d_in[9];
    const float* g2    = (const float*)d_in[10];
    const float* beta2 = (const float*)d_in[11];
    const float* m2    = (const float*)d_in[12];
    const float* v2    = (const float*)d_in[13];
    const float* W3    = (const float*)d_in[14];
    const float* b3    = (const float*)d_in[15];
    float* out = (float*)d_out;

    cudaFuncSetAttribute(main_kernel, cudaFuncAttributeMaxDynamicSharedMemorySize, SM_TOTAL);

    prep_base<<<dim3(4, 16), 128>>>(rep, W1, b1, g1, beta1, m1, v1);
    prep_emb <<<D_, H1_>>>(emb, W1, g1, v1);
    prep_cw  <<<(D_ * H1_ / 4) / 256, 256>>>(W1, g1, v1);
    prep_w2  <<<(H1_ * H2_) / 256, 256>>>(W2, b2, g2, beta2, m2, v2);
    main_kernel<<<NCTA, NTHR, SM_TOTAL>>>(rep, W3, b3, out);
}